// round 4
// baseline (speedup 1.0000x reference)
#include <cuda_runtime.h>

// VolumeRenderer: NeRF-style compositing. One warp handles TWO adjacent rays
// (r = 2*warp, r+1), fully unrolled: all 10 float4 loads are issued before any
// dependent compute (front-batched MLP), and the two rays' scan/reduce chains
// interleave for ILP. Adjacent rays make each warp's traffic contiguous:
// 1KB density, 1KB depth, 3KB feature per warp.
//
//   deltas = diff(depth) with 1e10 sentinel
//   att    = exp(-density * deltas)
//   T      = inclusive cumprod(att)   (lane-local products + warp shfl scan)
//   w      = T * (1 - att)
//   feat_out[n,c] = sum_s w*feature ; depth_out[n] = sum_s w*depth
//
// Output: feat_out (N_RAYS*3 floats) then depth_out (N_RAYS floats).

#define N_RAYS    131072
#define N_SAMPLES 128
#define FAR_DELTA 1e10f

#define BLOCK_THREADS 256
#define RAYS_PER_WARP 2
#define RAYS_PER_BLOCK ((BLOCK_THREADS / 32) * RAYS_PER_WARP)  // 16

__global__ __launch_bounds__(BLOCK_THREADS)
void volrend_kernel(const float* __restrict__ density,
                    const float* __restrict__ feature,
                    const float* __restrict__ depth,
                    float* __restrict__ out)
{
    const unsigned FULL = 0xffffffffu;
    const int warp = (blockIdx.x * BLOCK_THREADS + threadIdx.x) >> 5;
    const int lane = threadIdx.x & 31;
    const long rA = (long)warp * 2;
    const long rB = rA + 1;

    // ---- front-batched coalesced float4 loads for BOTH rays ----
    const float4* dA = reinterpret_cast<const float4*>(density + rA * N_SAMPLES);
    const float4* zA = reinterpret_cast<const float4*>(depth   + rA * N_SAMPLES);
    const float4* fA = reinterpret_cast<const float4*>(feature + rA * (N_SAMPLES * 3));
    const float4* dB = reinterpret_cast<const float4*>(density + rB * N_SAMPLES);
    const float4* zB = reinterpret_cast<const float4*>(depth   + rB * N_SAMPLES);
    const float4* fB = reinterpret_cast<const float4*>(feature + rB * (N_SAMPLES * 3));

    float4 dnA = __ldcs(dA + lane);
    float4 dnB = __ldcs(dB + lane);
    float4 zvA = __ldcs(zA + lane);
    float4 zvB = __ldcs(zB + lane);
    float4 f0A = __ldcs(fA + lane * 3 + 0);
    float4 f1A = __ldcs(fA + lane * 3 + 1);
    float4 f2A = __ldcs(fA + lane * 3 + 2);
    float4 f0B = __ldcs(fB + lane * 3 + 0);
    float4 f1B = __ldcs(fB + lane * 3 + 1);
    float4 f2B = __ldcs(fB + lane * 3 + 2);

    // next-lane first depth for the 4th delta of each lane
    float znA = __shfl_down_sync(FULL, zvA.x, 1);
    float znB = __shfl_down_sync(FULL, zvB.x, 1);

    // ---- attenuation (interleaved A/B for ILP) ----
    float a0A = __expf(-dnA.x * (zvA.y - zvA.x));
    float a0B = __expf(-dnB.x * (zvB.y - zvB.x));
    float a1A = __expf(-dnA.y * (zvA.z - zvA.y));
    float a1B = __expf(-dnB.y * (zvB.z - zvB.y));
    float a2A = __expf(-dnA.z * (zvA.w - zvA.z));
    float a2B = __expf(-dnB.z * (zvB.w - zvB.z));
    float d3A = (lane == 31) ? FAR_DELTA : (znA - zvA.w);
    float d3B = (lane == 31) ? FAR_DELTA : (znB - zvB.w);
    float a3A = __expf(-dnA.w * d3A);
    float a3B = __expf(-dnB.w * d3B);

    // lane-local inclusive products
    float p0A = a0A,        p0B = a0B;
    float p1A = p0A * a1A,  p1B = p0B * a1B;
    float p2A = p1A * a2A,  p2B = p1B * a2B;
    float p3A = p2A * a3A,  p3B = p2B * a3B;

    // warp-inclusive product scan of lane totals (both rays in lockstep)
    float sA = p3A, sB = p3B;
    #pragma unroll
    for (int off = 1; off < 32; off <<= 1) {
        float vA = __shfl_up_sync(FULL, sA, off);
        float vB = __shfl_up_sync(FULL, sB, off);
        if (lane >= off) { sA *= vA; sB *= vB; }
    }
    float exA = __shfl_up_sync(FULL, sA, 1);
    float exB = __shfl_up_sync(FULL, sB, 1);
    if (lane == 0) { exA = 1.0f; exB = 1.0f; }

    // weights
    float w0A = (exA * p0A) * (1.0f - a0A), w0B = (exB * p0B) * (1.0f - a0B);
    float w1A = (exA * p1A) * (1.0f - a1A), w1B = (exB * p1B) * (1.0f - a1B);
    float w2A = (exA * p2A) * (1.0f - a2A), w2B = (exB * p2B) * (1.0f - a2B);
    float w3A = (exA * p3A) * (1.0f - a3A), w3B = (exB * p3B) * (1.0f - a3B);

    // feature dots; sample k channels unpacked from 3 float4s:
    //   s0=(f0.x f0.y f0.z) s1=(f0.w f1.x f1.y) s2=(f1.z f1.w f2.x) s3=(f2.y f2.z f2.w)
    float fxA = w0A*f0A.x + w1A*f0A.w + w2A*f1A.z + w3A*f2A.y;
    float fyA = w0A*f0A.y + w1A*f1A.x + w2A*f1A.w + w3A*f2A.z;
    float fzA = w0A*f0A.z + w1A*f1A.y + w2A*f2A.x + w3A*f2A.w;
    float dsA = w0A*zvA.x + w1A*zvA.y + w2A*zvA.z + w3A*zvA.w;
    float fxB = w0B*f0B.x + w1B*f0B.w + w2B*f1B.z + w3B*f2B.y;
    float fyB = w0B*f0B.y + w1B*f1B.x + w2B*f1B.w + w3B*f2B.z;
    float fzB = w0B*f0B.z + w1B*f1B.y + w2B*f2B.x + w3B*f2B.w;
    float dsB = w0B*zvB.x + w1B*zvB.y + w2B*zvB.z + w3B*zvB.w;

    // warp reduction of the 8 accumulators
    #pragma unroll
    for (int off = 16; off > 0; off >>= 1) {
        fxA += __shfl_xor_sync(FULL, fxA, off);
        fyA += __shfl_xor_sync(FULL, fyA, off);
        fzA += __shfl_xor_sync(FULL, fzA, off);
        dsA += __shfl_xor_sync(FULL, dsA, off);
        fxB += __shfl_xor_sync(FULL, fxB, off);
        fyB += __shfl_xor_sync(FULL, fyB, off);
        fzB += __shfl_xor_sync(FULL, fzB, off);
        dsB += __shfl_xor_sync(FULL, dsB, off);
    }

    // every lane holds the sums; spread the 8 stores across lanes 0-7
    if (lane == 0)      out[rA * 3 + 0] = fxA;
    else if (lane == 1) out[rA * 3 + 1] = fyA;
    else if (lane == 2) out[rA * 3 + 2] = fzA;
    else if (lane == 3) out[(long)N_RAYS * 3 + rA] = dsA;
    else if (lane == 4) out[rB * 3 + 0] = fxB;
    else if (lane == 5) out[rB * 3 + 1] = fyB;
    else if (lane == 6) out[rB * 3 + 2] = fzB;
    else if (lane == 7) out[(long)N_RAYS * 3 + rB] = dsB;
}

extern "C" void kernel_launch(void* const* d_in, const int* in_sizes, int n_in,
                              void* d_out, int out_size)
{
    const float* density = (const float*)d_in[0];
    const float* feature = (const float*)d_in[1];
    const float* depth   = (const float*)d_in[2];
    float* out = (float*)d_out;

    int blocks = N_RAYS / RAYS_PER_BLOCK;   // 8192
    volrend_kernel<<<blocks, BLOCK_THREADS>>>(density, feature, depth, out);
}

// round 5
// speedup vs baseline: 1.1127x; 1.1127x over previous
#include <cuda_runtime.h>

// VolumeRenderer: NeRF-style compositing. One warp per ray; lane l owns
// samples [4l, 4l+3]. 128-thread CTAs (4 warps) for fine-grained scheduling;
// the three feature LDGs (75% of bytes) are issued first in the front batch.
//
//   deltas = diff(depth) with 1e10 sentinel
//   att    = exp(-density * deltas)
//   T      = inclusive cumprod(att)   (lane-local products + warp shfl scan)
//   w      = T * (1 - att)
//   feat_out[n,c] = sum_s w*feature ; depth_out[n] = sum_s w*depth
//
// Output: feat_out (N_RAYS*3 floats) then depth_out (N_RAYS floats).

#define N_RAYS    131072
#define N_SAMPLES 128
#define FAR_DELTA 1e10f

#define BLOCK_THREADS 128
#define WARPS_PER_BLOCK (BLOCK_THREADS / 32)

__global__ __launch_bounds__(BLOCK_THREADS)
void volrend_kernel(const float* __restrict__ density,
                    const float* __restrict__ feature,
                    const float* __restrict__ depth,
                    float* __restrict__ out)
{
    const unsigned FULL = 0xffffffffu;
    const int gwarp = (blockIdx.x * BLOCK_THREADS + threadIdx.x) >> 5;
    const int lane  = threadIdx.x & 31;
    const long r = gwarp;

    const float4* f4p = reinterpret_cast<const float4*>(feature + r * (N_SAMPLES * 3));
    const float4* d4p = reinterpret_cast<const float4*>(density + r * N_SAMPLES);
    const float4* z4p = reinterpret_cast<const float4*>(depth   + r * N_SAMPLES);

    // front-batched streaming loads; feature (big stream) first
    float4 f0 = __ldcs(f4p + lane * 3 + 0);
    float4 f1 = __ldcs(f4p + lane * 3 + 1);
    float4 f2 = __ldcs(f4p + lane * 3 + 2);
    float4 dn = __ldcs(d4p + lane);
    float4 z  = __ldcs(z4p + lane);

    // depth of first sample in the NEXT lane (this lane's 4th delta)
    float z_next = __shfl_down_sync(FULL, z.x, 1);

    float del0 = z.y - z.x;
    float del1 = z.z - z.y;
    float del2 = z.w - z.z;
    float del3 = (lane == 31) ? FAR_DELTA : (z_next - z.w);

    float a0 = __expf(-dn.x * del0);
    float a1 = __expf(-dn.y * del1);
    float a2 = __expf(-dn.z * del2);
    float a3 = __expf(-dn.w * del3);

    // lane-local inclusive products
    float p0 = a0;
    float p1 = p0 * a1;
    float p2 = p1 * a2;
    float p3 = p2 * a3;

    // warp-inclusive product scan of lane totals -> exclusive prefix
    float s = p3;
    #pragma unroll
    for (int off = 1; off < 32; off <<= 1) {
        float v = __shfl_up_sync(FULL, s, off);
        if (lane >= off) s *= v;
    }
    float excl = __shfl_up_sync(FULL, s, 1);
    if (lane == 0) excl = 1.0f;

    // weights
    float w0 = (excl * p0) * (1.0f - a0);
    float w1 = (excl * p1) * (1.0f - a1);
    float w2 = (excl * p2) * (1.0f - a2);
    float w3 = (excl * p3) * (1.0f - a3);

    // feature dot products; sample k channels unpacked from the 3 float4s:
    //   s0 = (f0.x f0.y f0.z)  s1 = (f0.w f1.x f1.y)
    //   s2 = (f1.z f1.w f2.x)  s3 = (f2.y f2.z f2.w)
    float fx = w0 * f0.x + w1 * f0.w + w2 * f1.z + w3 * f2.y;
    float fy = w0 * f0.y + w1 * f1.x + w2 * f1.w + w3 * f2.z;
    float fz = w0 * f0.z + w1 * f1.y + w2 * f2.x + w3 * f2.w;
    float ds = w0 * z.x  + w1 * z.y  + w2 * z.z  + w3 * z.w;

    // warp reduction of the 4 accumulators
    #pragma unroll
    for (int off = 16; off > 0; off >>= 1) {
        fx += __shfl_xor_sync(FULL, fx, off);
        fy += __shfl_xor_sync(FULL, fy, off);
        fz += __shfl_xor_sync(FULL, fz, off);
        ds += __shfl_xor_sync(FULL, ds, off);
    }

    // every lane holds the sums after the butterfly; spread the 4 stores
    if (lane == 0)      out[r * 3 + 0] = fx;
    else if (lane == 1) out[r * 3 + 1] = fy;
    else if (lane == 2) out[r * 3 + 2] = fz;
    else if (lane == 3) out[(long)N_RAYS * 3 + r] = ds;
}

extern "C" void kernel_launch(void* const* d_in, const int* in_sizes, int n_in,
                              void* d_out, int out_size)
{
    const float* density = (const float*)d_in[0];
    const float* feature = (const float*)d_in[1];
    const float* depth   = (const float*)d_in[2];
    float* out = (float*)d_out;

    int blocks = N_RAYS / WARPS_PER_BLOCK;   // 32768 CTAs, one warp per ray
    volrend_kernel<<<blocks, BLOCK_THREADS>>>(density, feature, depth, out);
}